// round 6
// baseline (speedup 1.0000x reference)
#include <cuda_runtime.h>
#include <math.h>
#include <stdint.h>

#define NB   4
#define LSEQ 4096
#define EMB  1024
#define NH   16
#define HD   64
#define WIN  256
#define OV   32
#define KWIN 320      // WIN + 2*OV
#define NWIN 16       // LSEQ / WIN

// Scratch (device globals -- no allocation allowed)
__device__ float g_q[(size_t)NB * LSEQ * EMB];
__device__ float g_k[(size_t)NB * LSEQ * EMB];
__device__ float g_v[(size_t)NB * LSEQ * EMB];
__device__ float g_att[(size_t)NB * LSEQ * EMB];

// ===========================================================================
// helpers
// ===========================================================================
__device__ __forceinline__ uint32_t smem_u32(const void* p) {
    uint32_t a;
    asm("{ .reg .u64 t; cvta.to.shared.u64 t, %1; cvt.u32.u64 %0, t; }"
        : "=r"(a) : "l"(p));
    return a;
}

// round-to-nearest-even bf16 of a float's bit pattern (normal range)
__device__ __forceinline__ uint32_t bf16_rn_bits(float x) {
    uint32_t xi = __float_as_uint(x);
    return (xi + 0x7FFFu + ((xi >> 16) & 1u)) >> 16;
}

// A-split: source x -> K' pattern [hi, hi, lo, lo]
//   word0 = hi | hi<<16 ; word1 = lo | lo<<16
__device__ __forceinline__ uint2 splitA(float x) {
    uint32_t xi = __float_as_uint(x);
    uint32_t h  = xi >> 16;                                  // truncated bf16
    float r = x - __uint_as_float(xi & 0xFFFF0000u);         // exact residual
    uint32_t l  = bf16_rn_bits(r);
    return make_uint2(h | (h << 16), l | (l << 16));
}

// B-split: source x -> K' pattern [hi, lo, hi, lo]
//   both words = hi | lo<<16
__device__ __forceinline__ uint32_t splitB(float x) {
    uint32_t xi = __float_as_uint(x);
    uint32_t h  = xi >> 16;
    float r = x - __uint_as_float(xi & 0xFFFF0000u);
    uint32_t l  = bf16_rn_bits(r);
    return h | (l << 16);
}

#define LDMATRIX_X4(r0, r1, r2, r3, addr) \
    asm volatile("ldmatrix.sync.aligned.m8n8.x4.shared.b16 {%0,%1,%2,%3}, [%4];" \
                 : "=r"(r0), "=r"(r1), "=r"(r2), "=r"(r3) : "r"(addr))

#define MMA_BF16(c, a0, a1, a2, a3, b0, b1) \
    asm volatile("mma.sync.aligned.m16n8k16.row.col.f32.bf16.bf16.f32 " \
                 "{%0,%1,%2,%3}, {%4,%5,%6,%7}, {%8,%9}, {%0,%1,%2,%3};" \
                 : "+f"((c)[0]), "+f"((c)[1]), "+f"((c)[2]), "+f"((c)[3]) \
                 : "r"(a0), "r"(a1), "r"(a2), "r"(a3), "r"(b0), "r"(b1))

// ---------------------------------------------------------------------------
// Kernel 1: fused q/k/v per-head projection (fp32, vectorized LDS.128).
// ---------------------------------------------------------------------------
#define PROJ_STRIDE 68

__global__ __launch_bounds__(256) void proj_kernel(
    const float* __restrict__ vals, const float* __restrict__ keys,
    const float* __restrict__ qrs,
    const float* __restrict__ Wv, const float* __restrict__ Wk,
    const float* __restrict__ Wq)
{
    __shared__ float sW[64 * PROJ_STRIDE];
    __shared__ float sX[64 * PROJ_STRIDE];

    const float* X; const float* W; float* O;
    switch (blockIdx.z) {
        case 0:  X = vals; W = Wv; O = g_v; break;
        case 1:  X = keys; W = Wk; O = g_k; break;
        default: X = qrs;  W = Wq; O = g_q; break;
    }
    const int h  = blockIdx.y;
    const size_t r0 = (size_t)blockIdx.x * 64;
    const int t  = threadIdx.x;

    for (int i = t; i < 64 * 16; i += 256) {
        int r = i >> 4, g = i & 15;
        *(float4*)&sW[r * PROJ_STRIDE + g * 4] = *(const float4*)&W[r * 64 + g * 4];
        *(float4*)&sX[r * PROJ_STRIDE + g * 4] =
            *(const float4*)&X[(r0 + r) * EMB + h * HD + g * 4];
    }
    __syncthreads();

    const int tx = t & 15, ty = t >> 4;
    float acc[4][4] = {};
    #pragma unroll
    for (int d4 = 0; d4 < 16; d4++) {
        float4 a[4], b[4];
        #pragma unroll
        for (int i = 0; i < 4; i++)
            a[i] = *(const float4*)&sX[(ty * 4 + i) * PROJ_STRIDE + d4 * 4];
        #pragma unroll
        for (int j = 0; j < 4; j++)
            b[j] = *(const float4*)&sW[(tx * 4 + j) * PROJ_STRIDE + d4 * 4];
        #pragma unroll
        for (int i = 0; i < 4; i++)
            #pragma unroll
            for (int j = 0; j < 4; j++)
                acc[i][j] += a[i].x * b[j].x + a[i].y * b[j].y +
                             a[i].z * b[j].z + a[i].w * b[j].w;
    }

    #pragma unroll
    for (int i = 0; i < 4; i++) {
        float4 o4 = make_float4(acc[i][0], acc[i][1], acc[i][2], acc[i][3]);
        *(float4*)&O[(r0 + ty * 4 + i) * EMB + h * HD + tx * 4] = o4;
    }
}

// ---------------------------------------------------------------------------
// Kernel 2: overlapping-window attention (scalar fp32, unchanged).
// ---------------------------------------------------------------------------
__global__ __launch_bounds__(256, 1) void attn_kernel(const int* __restrict__ mask)
{
    extern __shared__ float sm[];
    float* sK = sm;
    float* sV = sm + KWIN * HD;

    const int w  = blockIdx.x;
    const int h  = blockIdx.y;
    const int nb = blockIdx.z;
    const int t  = threadIdx.x;
    const size_t qbase = (size_t)nb * LSEQ + (size_t)w * WIN;

    for (int i = t; i < WIN * HD; i += 256) {
        int r = i >> 6, dd = i & 63;
        sK[r * 64 + ((dd + r) & 63)] = g_q[(qbase + r) * EMB + h * HD + dd];
    }
    __syncthreads();
    float q[64];
    #pragma unroll
    for (int i = 0; i < 64; i++) q[i] = sK[t * 64 + ((i + t) & 63)];
    __syncthreads();

    const float4* gk4 = (const float4*)g_k;
    const float4* gv4 = (const float4*)g_v;
    float4* sK4 = (float4*)sK;
    float4* sV4 = (float4*)sV;
    for (int i = t; i < KWIN * (HD / 4); i += 256) {
        int j = i >> 4, u = i & 15;
        int tok = w * WIN + j - OV;
        float4 kk = make_float4(0.f, 0.f, 0.f, 0.f);
        float4 vv = make_float4(0.f, 0.f, 0.f, 0.f);
        if ((unsigned)tok < (unsigned)LSEQ) {
            size_t idx = (((size_t)nb * LSEQ + tok) * EMB + h * HD) / 4 + u;
            kk = gk4[idx];
            vv = gv4[idx];
        }
        sK4[i] = kk;
        sV4[i] = vv;
    }
    __syncthreads();

    const int qtok = w * WIN + t;
    const bool qv  = mask[(size_t)nb * LSEQ + qtok] != 0;

    float m = -INFINITY, l = 0.f;
    float acc[64];
    #pragma unroll
    for (int i = 0; i < 64; i++) acc[i] = 0.f;

    for (int c = 0; c < KWIN / 16; c++) {
        float s[16];
        float cmax = -INFINITY;
        #pragma unroll
        for (int jj = 0; jj < 16; jj++) {
            const int j = c * 16 + jj;
            const float4* kr = (const float4*)(sK + j * 64);
            float s0 = 0.f, s1 = 0.f, s2 = 0.f, s3 = 0.f;
            #pragma unroll
            for (int u = 0; u < 16; u++) {
                float4 k4 = kr[u];
                s0 += q[4 * u + 0] * k4.x;
                s1 += q[4 * u + 1] * k4.y;
                s2 += q[4 * u + 2] * k4.z;
                s3 += q[4 * u + 3] * k4.w;
            }
            float sc = ((s0 + s1) + (s2 + s3)) * 0.125f;
            if (!qv) sc = -1.25e9f;
            int tok = w * WIN + j - OV;
            if ((unsigned)tok >= (unsigned)LSEQ) sc = -INFINITY;
            s[jj] = sc;
            cmax = fmaxf(cmax, sc);
        }
        const float mn = fmaxf(m, cmax);
        if (mn == -INFINITY) continue;
        const float corr = __expf(m - mn);
        l *= corr;
        #pragma unroll
        for (int i = 0; i < 64; i++) acc[i] *= corr;
        #pragma unroll
        for (int jj = 0; jj < 16; jj++) {
            const int j = c * 16 + jj;
            const float p = __expf(s[jj] - mn);
            l += p;
            const float4* vr = (const float4*)(sV + j * 64);
            #pragma unroll
            for (int u = 0; u < 16; u++) {
                float4 v4 = vr[u];
                acc[4 * u + 0] += p * v4.x;
                acc[4 * u + 1] += p * v4.y;
                acc[4 * u + 2] += p * v4.z;
                acc[4 * u + 3] += p * v4.w;
            }
        }
        m = mn;
    }

    const float inv = (l > 0.f) ? (1.f / l) : 0.f;

    __syncthreads();
    #pragma unroll
    for (int i = 0; i < 64; i++) sK[t * 64 + ((i + t) & 63)] = acc[i] * inv;
    __syncthreads();
    for (int i = t; i < WIN * HD; i += 256) {
        int r = i >> 6, dd = i & 63;
        g_att[(qbase + r) * EMB + h * HD + dd] = sK[r * 64 + ((dd + r) & 63)];
    }
}

// ---------------------------------------------------------------------------
// Kernel 3: output projection via mma.sync bf16 with hi/lo split (K'=4K).
// out[16384,1024] = g_att @ Wf^T + bf,  D[m][n] = sum_k A[m][k]*B[n][k]
// Block tile 128x128, BK=64 bf16 (16 src fp32), 8 warps (2M x 4N),
// warp tile 64x32, XOR-swizzled smem, register double-buffered loads.
// grid: (EMB/128, NB*LSEQ/128) = (8, 128), block 256.
// ---------------------------------------------------------------------------
#define KTILES     64          // K'=4096 bf16 / BK=64
#define ABUF_BYTES 16384       // 128 rows * 128 B
#define BUF_BYTES  32768       // A + B per stage
#define SMEM_GEMM  (2 * BUF_BYTES)

__global__ __launch_bounds__(256, 1) void out_gemm_mma(
    const float* __restrict__ Wf, const float* __restrict__ bf,
    float* __restrict__ out)
{
    extern __shared__ char smc[];
    const uint32_t sb = smem_u32(smc);
    const int tid  = threadIdx.x, lane = tid & 31, wid = tid >> 5;
    const int wm   = (wid & 1) * 64;          // warp M offset
    const int wn   = (wid >> 1) * 32;         // warp N offset
    const size_t m0 = (size_t)blockIdx.y * 128;
    const int e0   = blockIdx.x * 128;

    // ldmatrix per-lane patterns
    const int a_lrow = lane & 15;             // rows 0..15 of m-tile
    const int a_half = lane >> 4;             // k granule half
    const int b_lrow = (lane & 7) + ((lane & 16) >> 1);  // n row within 16
    const int b_half = (lane >> 3) & 1;

    const int ldr = tid >> 2;                 // load row (0..63) + it*64
    const int ldf = tid & 3;                  // source float4 index 0..3

    float c[4][4][4];
    #pragma unroll
    for (int i = 0; i < 4; i++)
        #pragma unroll
        for (int j = 0; j < 4; j++)
            #pragma unroll
            for (int u = 0; u < 4; u++) c[i][j][u] = 0.f;

    float4 ra[2], rb[2];

    // ---- prefetch tile 0 ----
    #pragma unroll
    for (int it = 0; it < 2; it++) {
        int r = it * 64 + ldr;
        ra[it] = *(const float4*)&g_att[(m0 + r) * EMB + ldf * 4];
        rb[it] = *(const float4*)&Wf[(size_t)(e0 + r) * EMB + ldf * 4];
    }

    // store tile 0
    #pragma unroll
    for (int it = 0; it < 2; it++) {
        int r = it * 64 + ldr;
        uint32_t rm = (uint32_t)(r & 7);
        char* arow = smc + r * 128;
        char* brow = smc + ABUF_BYTES + r * 128;
        uint2 wx = splitA(ra[it].x), wy = splitA(ra[it].y),
              wz = splitA(ra[it].z), ww = splitA(ra[it].w);
        *(uint4*)(arow + ((((uint32_t)(2 * ldf))     ^ rm) << 4)) =
            make_uint4(wx.x, wx.y, wy.x, wy.y);
        *(uint4*)(arow + ((((uint32_t)(2 * ldf + 1)) ^ rm) << 4)) =
            make_uint4(wz.x, wz.y, ww.x, ww.y);
        uint32_t bx = splitB(rb[it].x), by = splitB(rb[it].y),
                 bz = splitB(rb[it].z), bw = splitB(rb[it].w);
        *(uint4*)(brow + ((((uint32_t)(2 * ldf))     ^ rm) << 4)) =
            make_uint4(bx, bx, by, by);
        *(uint4*)(brow + ((((uint32_t)(2 * ldf + 1)) ^ rm) << 4)) =
            make_uint4(bz, bz, bw, bw);
    }
    __syncthreads();

    for (int t = 0; t < KTILES; t++) {
        // ---- issue gmem loads for tile t+1 ----
        if (t + 1 < KTILES) {
            const int ks = (t + 1) * 16;
            #pragma unroll
            for (int it = 0; it < 2; it++) {
                int r = it * 64 + ldr;
                ra[it] = *(const float4*)&g_att[(m0 + r) * EMB + ks + ldf * 4];
                rb[it] = *(const float4*)&Wf[(size_t)(e0 + r) * EMB + ks + ldf * 4];
            }
        }

        // ---- compute from smem buffer t&1 ----
        const uint32_t abase = sb + (uint32_t)(t & 1) * BUF_BYTES;
        const uint32_t bbase = abase + ABUF_BYTES;
        #pragma unroll
        for (int s = 0; s < 4; s++) {
            uint32_t a[4][4];
            #pragma unroll
            for (int mt = 0; mt < 4; mt++) {
                int row = wm + mt * 16 + a_lrow;
                uint32_t addr = abase + (uint32_t)row * 128u +
                    ((uint32_t)((2 * s + a_half) ^ (row & 7)) << 4);
                LDMATRIX_X4(a[mt][0], a[mt][1], a[mt][2], a[mt][3], addr);
            }
            uint32_t b[8];
            #pragma unroll
            for (int nt = 0; nt < 2; nt++) {
                int row = wn + nt * 16 + b_lrow;
                uint32_t addr = bbase + (uint32_t)row * 128u +
                    ((uint32_t)((2 * s + b_half) ^ (row & 7)) << 4);
                LDMATRIX_X4(b[nt * 4 + 0], b[nt * 4 + 1],
                            b[nt * 4 + 2], b[nt * 4 + 3], addr);
            }
            #pragma unroll
            for (int mt = 0; mt < 4; mt++)
                #pragma unroll
                for (int nf = 0; nf < 4; nf++)
                    MMA_BF16(c[mt][nf], a[mt][0], a[mt][1], a[mt][2], a[mt][3],
                             b[nf * 2], b[nf * 2 + 1]);
        }

        // ---- store tile t+1 into the other buffer ----
        if (t + 1 < KTILES) {
            const int nbuf = (t + 1) & 1;
            #pragma unroll
            for (int it = 0; it < 2; it++) {
                int r = it * 64 + ldr;
                uint32_t rm = (uint32_t)(r & 7);
                char* arow = smc + nbuf * BUF_BYTES + r * 128;
                char* brow = smc + nbuf * BUF_BYTES + ABUF_BYTES + r * 128;
                uint2 wx = splitA(ra[it].x), wy = splitA(ra[it].y),
                      wz = splitA(ra[it].z), ww = splitA(ra[it].w);
                *(uint4*)(arow + ((((uint32_t)(2 * ldf))     ^ rm) << 4)) =
                    make_uint4(wx.x, wx.y, wy.x, wy.y);
                *(uint4*)(arow + ((((uint32_t)(2 * ldf + 1)) ^ rm) << 4)) =
                    make_uint4(wz.x, wz.y, ww.x, ww.y);
                uint32_t bx = splitB(rb[it].x), by = splitB(rb[it].y),
                         bz = splitB(rb[it].z), bw = splitB(rb[it].w);
                *(uint4*)(brow + ((((uint32_t)(2 * ldf))     ^ rm) << 4)) =
                    make_uint4(bx, bx, by, by);
                *(uint4*)(brow + ((((uint32_t)(2 * ldf + 1)) ^ rm) << 4)) =
                    make_uint4(bz, bz, bw, bw);
            }
            __syncthreads();
        }
    }

    // ---- epilogue: bias + direct stores (float2) ----
    #pragma unroll
    for (int mt = 0; mt < 4; mt++) {
        #pragma unroll
        for (int nf = 0; nf < 4; nf++) {
            int m   = (int)m0 + wm + mt * 16 + (lane >> 2);
            int col = e0 + wn + nf * 8 + (lane & 3) * 2;
            float b0 = bf[col], b1 = bf[col + 1];
            float2 v0 = make_float2(c[mt][nf][0] + b0, c[mt][nf][1] + b1);
            float2 v1 = make_float2(c[mt][nf][2] + b0, c[mt][nf][3] + b1);
            *(float2*)&out[(size_t)m * EMB + col] = v0;
            *(float2*)&out[(size_t)(m + 8) * EMB + col] = v1;
        }
    }
}

// ---------------------------------------------------------------------------
extern "C" void kernel_launch(void* const* d_in, const int* in_sizes, int n_in,
                              void* d_out, int out_size)
{
    const float* vals = (const float*)d_in[0];
    const float* keys = (const float*)d_in[1];
    const float* qrs  = (const float*)d_in[2];
    const int*   mask = (const int*)d_in[3];
    const float* Wv   = (const float*)d_in[4];
    const float* Wk   = (const float*)d_in[5];
    const float* Wq   = (const float*)d_in[6];
    const float* Wf   = (const float*)d_in[7];
    const float* bf   = (const float*)d_in[8];
    float* out = (float*)d_out;

    const int attn_smem = 2 * KWIN * HD * (int)sizeof(float);  // 160 KB
    cudaFuncSetAttribute(attn_kernel,
                         cudaFuncAttributeMaxDynamicSharedMemorySize, attn_smem);
    cudaFuncSetAttribute(out_gemm_mma,
                         cudaFuncAttributeMaxDynamicSharedMemorySize, SMEM_GEMM);

    proj_kernel<<<dim3(NB * LSEQ / 64, NH, 3), 256>>>(vals, keys, qrs, Wv, Wk, Wq);
    attn_kernel<<<dim3(NWIN, NH, NB), 256, attn_smem>>>(mask);
    out_gemm_mma<<<dim3(EMB / 128, NB * LSEQ / 128), 256, SMEM_GEMM>>>(Wf, bf, out);
}

// round 7
// speedup vs baseline: 1.9049x; 1.9049x over previous
#include <cuda_runtime.h>
#include <math.h>
#include <stdint.h>

#define NB   4
#define LSEQ 4096
#define EMB  1024
#define NH   16
#define HD   64
#define WIN  256
#define OV   32
#define KWIN 320      // WIN + 2*OV
#define NWIN 16       // LSEQ / WIN

// Scratch (device globals -- no allocation allowed)
__device__ float g_q[(size_t)NB * LSEQ * EMB];
__device__ float g_k[(size_t)NB * LSEQ * EMB];
__device__ float g_v[(size_t)NB * LSEQ * EMB];
__device__ float g_att[(size_t)NB * LSEQ * EMB];

// ===========================================================================
// helpers
// ===========================================================================
__device__ __forceinline__ uint32_t smem_u32(const void* p) {
    uint32_t a;
    asm("{ .reg .u64 t; cvta.to.shared.u64 t, %1; cvt.u32.u64 %0, t; }"
        : "=r"(a) : "l"(p));
    return a;
}

__device__ __forceinline__ void cp_async16(uint32_t s, const void* g) {
    asm volatile("cp.async.cg.shared.global [%0], [%1], 16;" :: "r"(s), "l"(g));
}
#define CP_COMMIT() asm volatile("cp.async.commit_group;" ::: "memory")
#define CP_WAIT(N)  asm volatile("cp.async.wait_group %0;" :: "n"(N) : "memory")

// D = A(16x8) * B(8x8) + D, tf32 operands as raw fp32 bits (HW truncates)
#define MMA_TF32(c, a0, a1, a2, a3, b0, b1) \
    asm volatile("mma.sync.aligned.m16n8k8.row.col.f32.tf32.tf32.f32 " \
                 "{%0,%1,%2,%3}, {%4,%5,%6,%7}, {%8,%9}, {%0,%1,%2,%3};" \
                 : "+f"((c)[0]), "+f"((c)[1]), "+f"((c)[2]), "+f"((c)[3]) \
                 : "r"(a0), "r"(a1), "r"(a2), "r"(a3), "r"(b0), "r"(b1))

// ---------------------------------------------------------------------------
// Kernel 1: fused q/k/v per-head projection (R2 scalar version, known 340us).
// out[r, h, e] = sum_d X[r, h, d] * W[e, d]
// grid: (NB*LSEQ/64, NH, 3), block: 256
// ---------------------------------------------------------------------------
__global__ __launch_bounds__(256) void proj_kernel(
    const float* __restrict__ vals, const float* __restrict__ keys,
    const float* __restrict__ qrs,
    const float* __restrict__ Wv, const float* __restrict__ Wk,
    const float* __restrict__ Wq)
{
    __shared__ float sW[64][65];
    __shared__ float sX[64][65];

    const float* X; const float* W; float* O;
    switch (blockIdx.z) {
        case 0:  X = vals; W = Wv; O = g_v; break;
        case 1:  X = keys; W = Wk; O = g_k; break;
        default: X = qrs;  W = Wq; O = g_q; break;
    }
    const int h  = blockIdx.y;
    const size_t r0 = (size_t)blockIdx.x * 64;
    const int t  = threadIdx.x;

    for (int i = t; i < 64 * 64; i += 256) sW[i >> 6][i & 63] = W[i];
    for (int i = t; i < 64 * 64; i += 256) {
        int r = i >> 6, dd = i & 63;
        sX[r][dd] = X[(r0 + r) * EMB + h * HD + dd];
    }
    __syncthreads();

    const int tx = t & 15, ty = t >> 4;
    float acc[4][4] = {};
    #pragma unroll 8
    for (int dd = 0; dd < 64; dd++) {
        float a[4], b[4];
        #pragma unroll
        for (int i = 0; i < 4; i++) a[i] = sX[ty * 4 + i][dd];
        #pragma unroll
        for (int j = 0; j < 4; j++) b[j] = sW[tx * 4 + j][dd];
        #pragma unroll
        for (int i = 0; i < 4; i++)
            #pragma unroll
            for (int j = 0; j < 4; j++) acc[i][j] += a[i] * b[j];
    }

    #pragma unroll
    for (int i = 0; i < 4; i++)
        #pragma unroll
        for (int j = 0; j < 4; j++)
            O[(r0 + ty * 4 + i) * EMB + h * HD + tx * 4 + j] = acc[i][j];
}

// ---------------------------------------------------------------------------
// Kernel 2: overlapping-window attention (scalar fp32, unchanged).
// ---------------------------------------------------------------------------
__global__ __launch_bounds__(256, 1) void attn_kernel(const int* __restrict__ mask)
{
    extern __shared__ float sm[];
    float* sK = sm;
    float* sV = sm + KWIN * HD;

    const int w  = blockIdx.x;
    const int h  = blockIdx.y;
    const int nb = blockIdx.z;
    const int t  = threadIdx.x;
    const size_t qbase = (size_t)nb * LSEQ + (size_t)w * WIN;

    for (int i = t; i < WIN * HD; i += 256) {
        int r = i >> 6, dd = i & 63;
        sK[r * 64 + ((dd + r) & 63)] = g_q[(qbase + r) * EMB + h * HD + dd];
    }
    __syncthreads();
    float q[64];
    #pragma unroll
    for (int i = 0; i < 64; i++) q[i] = sK[t * 64 + ((i + t) & 63)];
    __syncthreads();

    const float4* gk4 = (const float4*)g_k;
    const float4* gv4 = (const float4*)g_v;
    float4* sK4 = (float4*)sK;
    float4* sV4 = (float4*)sV;
    for (int i = t; i < KWIN * (HD / 4); i += 256) {
        int j = i >> 4, u = i & 15;
        int tok = w * WIN + j - OV;
        float4 kk = make_float4(0.f, 0.f, 0.f, 0.f);
        float4 vv = make_float4(0.f, 0.f, 0.f, 0.f);
        if ((unsigned)tok < (unsigned)LSEQ) {
            size_t idx = (((size_t)nb * LSEQ + tok) * EMB + h * HD) / 4 + u;
            kk = gk4[idx];
            vv = gv4[idx];
        }
        sK4[i] = kk;
        sV4[i] = vv;
    }
    __syncthreads();

    const int qtok = w * WIN + t;
    const bool qv  = mask[(size_t)nb * LSEQ + qtok] != 0;

    float m = -INFINITY, l = 0.f;
    float acc[64];
    #pragma unroll
    for (int i = 0; i < 64; i++) acc[i] = 0.f;

    for (int c = 0; c < KWIN / 16; c++) {
        float s[16];
        float cmax = -INFINITY;
        #pragma unroll
        for (int jj = 0; jj < 16; jj++) {
            const int j = c * 16 + jj;
            const float4* kr = (const float4*)(sK + j * 64);
            float s0 = 0.f, s1 = 0.f, s2 = 0.f, s3 = 0.f;
            #pragma unroll
            for (int u = 0; u < 16; u++) {
                float4 k4 = kr[u];
                s0 += q[4 * u + 0] * k4.x;
                s1 += q[4 * u + 1] * k4.y;
                s2 += q[4 * u + 2] * k4.z;
                s3 += q[4 * u + 3] * k4.w;
            }
            float sc = ((s0 + s1) + (s2 + s3)) * 0.125f;
            if (!qv) sc = -1.25e9f;
            int tok = w * WIN + j - OV;
            if ((unsigned)tok >= (unsigned)LSEQ) sc = -INFINITY;
            s[jj] = sc;
            cmax = fmaxf(cmax, sc);
        }
        const float mn = fmaxf(m, cmax);
        if (mn == -INFINITY) continue;
        const float corr = __expf(m - mn);
        l *= corr;
        #pragma unroll
        for (int i = 0; i < 64; i++) acc[i] *= corr;
        #pragma unroll
        for (int jj = 0; jj < 16; jj++) {
            const int j = c * 16 + jj;
            const float p = __expf(s[jj] - mn);
            l += p;
            const float4* vr = (const float4*)(sV + j * 64);
            #pragma unroll
            for (int u = 0; u < 16; u++) {
                float4 v4 = vr[u];
                acc[4 * u + 0] += p * v4.x;
                acc[4 * u + 1] += p * v4.y;
                acc[4 * u + 2] += p * v4.z;
                acc[4 * u + 3] += p * v4.w;
            }
        }
        m = mn;
    }

    const float inv = (l > 0.f) ? (1.f / l) : 0.f;

    __syncthreads();
    #pragma unroll
    for (int i = 0; i < 64; i++) sK[t * 64 + ((i + t) & 63)] = acc[i] * inv;
    __syncthreads();
    for (int i = t; i < WIN * HD; i += 256) {
        int r = i >> 6, dd = i & 63;
        g_att[(qbase + r) * EMB + h * HD + dd] = sK[r * 64 + ((dd + r) & 63)];
    }
}

// ---------------------------------------------------------------------------
// Kernel 3: output projection via mma.sync tf32 (K=1024, no splitting).
// out[16384,1024] = g_att @ Wf^T + bf,  D[m][n] = sum_k A[m][k]*B[n][k]
// Block tile 128x128, BK=32 fp32, 3-stage cp.async pipeline, 8 warps (2Mx4N),
// warp tile 64x32.  smem rows stride 36 floats -> conflict-free frag loads
// (bank = 4*(lane>>2) + (lane&3), all 32 banks distinct).
// grid: (8, 128), block 256, 2 CTAs/SM.
// ---------------------------------------------------------------------------
#define BK        32
#define KTILES    (EMB / BK)            // 32
#define ROW_F     36                    // floats per smem row (144 B)
#define TILE_F    (128 * ROW_F)         // floats per A (or B) tile = 4608
#define STAGE_F   (2 * TILE_F)          // A + B per stage = 9216 floats
#define NSTAGE    3
#define SMEM_GEMM (NSTAGE * STAGE_F * 4)  // 110,592 bytes

__global__ __launch_bounds__(256, 2) void out_gemm_tf32(
    const float* __restrict__ Wf, const float* __restrict__ bf,
    float* __restrict__ out)
{
    extern __shared__ float sg[];
    const uint32_t sb = smem_u32(sg);
    const int tid  = threadIdx.x, lane = tid & 31, wid = tid >> 5;
    const int wm   = (wid & 1) * 64;
    const int wn   = (wid >> 1) * 32;
    const size_t m0 = (size_t)blockIdx.y * 128;
    const int e0   = blockIdx.x * 128;

    const int lr = lane >> 2;       // fragment row within 8
    const int lc = lane & 3;        // fragment k within 4

    // fill mapping: 4 chunks each for A and B per stage
    const int frow = tid >> 3;      // rows covered in 4 steps of 32
    const int fc   = tid & 7;       // 16B chunk within 32-float row

    float c[4][4][4];
    #pragma unroll
    for (int i = 0; i < 4; i++)
        #pragma unroll
        for (int j = 0; j < 4; j++)
            #pragma unroll
            for (int u = 0; u < 4; u++) c[i][j][u] = 0.f;

    // ---- issue one stage's loads ----
    auto issue = [&](int s) {
        const int buf = s % NSTAGE;
        const int k0  = s * BK;
        const uint32_t sa = sb + (uint32_t)(buf * STAGE_F) * 4u;
        const uint32_t sbb = sa + (uint32_t)TILE_F * 4u;
        #pragma unroll
        for (int it = 0; it < 4; it++) {
            const int r = it * 32 + frow;
            cp_async16(sa  + (uint32_t)(r * ROW_F + fc * 4) * 4u,
                       &g_att[(m0 + r) * EMB + k0 + fc * 4]);
            cp_async16(sbb + (uint32_t)(r * ROW_F + fc * 4) * 4u,
                       &Wf[(size_t)(e0 + r) * EMB + k0 + fc * 4]);
        }
        CP_COMMIT();
    };

    issue(0);
    issue(1);

    for (int t = 0; t < KTILES; t++) {
        if (t < KTILES - 1) { CP_WAIT(1); } else { CP_WAIT(0); }
        __syncthreads();

        if (t + 2 < KTILES) issue(t + 2);

        const int buf = t % NSTAGE;
        const float* As = sg + buf * STAGE_F;
        const float* Bs = As + TILE_F;

        #pragma unroll
        for (int ks = 0; ks < 4; ks++) {
            uint32_t a[4][4];
            #pragma unroll
            for (int mt = 0; mt < 4; mt++) {
                const int base = (wm + mt * 16 + lr) * ROW_F + ks * 8 + lc;
                a[mt][0] = __float_as_uint(As[base]);
                a[mt][1] = __float_as_uint(As[base + 8 * ROW_F]);
                a[mt][2] = __float_as_uint(As[base + 4]);
                a[mt][3] = __float_as_uint(As[base + 8 * ROW_F + 4]);
            }
            #pragma unroll
            for (int nf = 0; nf < 4; nf++) {
                const int bbase = (wn + nf * 8 + lr) * ROW_F + ks * 8 + lc;
                const uint32_t b0 = __float_as_uint(Bs[bbase]);
                const uint32_t b1 = __float_as_uint(Bs[bbase + 4]);
                #pragma unroll
                for (int mt = 0; mt < 4; mt++)
                    MMA_TF32(c[mt][nf], a[mt][0], a[mt][1], a[mt][2], a[mt][3],
                             b0, b1);
            }
        }
        __syncthreads();
    }

    // ---- epilogue: bias + direct stores ----
    #pragma unroll
    for (int mt = 0; mt < 4; mt++) {
        #pragma unroll
        for (int nf = 0; nf < 4; nf++) {
            const int m   = (int)m0 + wm + mt * 16 + lr;
            const int col = e0 + wn + nf * 8 + lc * 2;
            const float b0 = bf[col], b1 = bf[col + 1];
            float2 v0 = make_float2(c[mt][nf][0] + b0, c[mt][nf][1] + b1);
            float2 v1 = make_float2(c[mt][nf][2] + b0, c[mt][nf][3] + b1);
            *(float2*)&out[(size_t)m * EMB + col] = v0;
            *(float2*)&out[(size_t)(m + 8) * EMB + col] = v1;
        }
    }
}

// ---------------------------------------------------------------------------
extern "C" void kernel_launch(void* const* d_in, const int* in_sizes, int n_in,
                              void* d_out, int out_size)
{
    const float* vals = (const float*)d_in[0];
    const float* keys = (const float*)d_in[1];
    const float* qrs  = (const float*)d_in[2];
    const int*   mask = (const int*)d_in[3];
    const float* Wv   = (const float*)d_in[4];
    const float* Wk   = (const float*)d_in[5];
    const float* Wq   = (const float*)d_in[6];
    const float* Wf   = (const float*)d_in[7];
    const float* bf   = (const float*)d_in[8];
    float* out = (float*)d_out;

    const int attn_smem = 2 * KWIN * HD * (int)sizeof(float);  // 160 KB
    cudaFuncSetAttribute(attn_kernel,
                         cudaFuncAttributeMaxDynamicSharedMemorySize, attn_smem);
    cudaFuncSetAttribute(out_gemm_tf32,
                         cudaFuncAttributeMaxDynamicSharedMemorySize, SMEM_GEMM);

    proj_kernel<<<dim3(NB * LSEQ / 64, NH, 3), 256>>>(vals, keys, qrs, Wv, Wk, Wq);
    attn_kernel<<<dim3(NWIN, NH, NB), 256, attn_smem>>>(mask);
    out_gemm_tf32<<<dim3(EMB / 128, NB * LSEQ / 128), 256, SMEM_GEMM>>>(Wf, bf, out);
}